// round 1
// baseline (speedup 1.0000x reference)
#include <cuda_runtime.h>
#include <math.h>

#define NN 100000
#define EE 1600000
#define DD 64

// ---------------- scratch (device globals; no allocation allowed) ----------
__device__ float g_h[(size_t)NN * DD];   // X@W for current layer
__device__ float g_z[(size_t)NN * DD];   // layer-1 output (relu'd)
__device__ float g_as[NN];
__device__ float g_ad[NN];
__device__ int   g_counts[NN];
__device__ int   g_offs[NN + 1];
__device__ int   g_cursor[NN];
__device__ int   g_csr[EE];              // src node ids, grouped by dst
__device__ int   g_bsums[128];

// ---------------- CSR build ------------------------------------------------
__global__ void zero_counts_k() {
    int i = blockIdx.x * blockDim.x + threadIdx.x;
    if (i < NN) g_counts[i] = 0;
}

__global__ void hist_k(const int* __restrict__ dst) {
    int i = blockIdx.x * blockDim.x + threadIdx.x;
    if (i < EE) atomicAdd(&g_counts[dst[i]], 1);
}

// scanA: 98 blocks x 256 threads, 4 elems/thread (1024 elems/block)
__global__ void scanA_k() {
    __shared__ int warpSums[8];
    int b = blockIdx.x, t = threadIdx.x;
    int base = b * 1024 + t * 4;
    int c0 = (base + 0 < NN) ? g_counts[base + 0] : 0;
    int c1 = (base + 1 < NN) ? g_counts[base + 1] : 0;
    int c2 = (base + 2 < NN) ? g_counts[base + 2] : 0;
    int c3 = (base + 3 < NN) ? g_counts[base + 3] : 0;
    int tsum = c0 + c1 + c2 + c3;
    int lane = t & 31, wid = t >> 5;
    int v = tsum;
    #pragma unroll
    for (int d = 1; d < 32; d <<= 1) {
        int n = __shfl_up_sync(0xffffffffu, v, d);
        if (lane >= d) v += n;
    }
    if (lane == 31) warpSums[wid] = v;
    __syncthreads();
    if (wid == 0 && lane < 8) {
        int wv = warpSums[lane];
        #pragma unroll
        for (int d = 1; d < 8; d <<= 1) {
            int n = __shfl_up_sync(0xffu, wv, d);
            if (lane >= d) wv += n;
        }
        warpSums[lane] = wv;
    }
    __syncthreads();
    int exc = v - tsum + (wid > 0 ? warpSums[wid - 1] : 0);
    if (base + 0 < NN) g_offs[base + 0] = exc;
    if (base + 1 < NN) g_offs[base + 1] = exc + c0;
    if (base + 2 < NN) g_offs[base + 2] = exc + c0 + c1;
    if (base + 3 < NN) g_offs[base + 3] = exc + c0 + c1 + c2;
    if (t == 255) g_bsums[b] = warpSums[7];
}

__global__ void scanB_k(int nblocks) {
    __shared__ int sm[128];
    int t = threadIdx.x;
    sm[t] = (t < nblocks) ? g_bsums[t] : 0;
    __syncthreads();
    #pragma unroll
    for (int d = 1; d < 128; d <<= 1) {
        int v = (t >= d) ? sm[t - d] : 0;
        __syncthreads();
        sm[t] += v;
        __syncthreads();
    }
    if (t < nblocks) g_bsums[t] = (t == 0) ? 0 : sm[t - 1];
}

__global__ void scanC_k() {
    int i = blockIdx.x * blockDim.x + threadIdx.x;
    if (i < NN) {
        int v = g_offs[i] + g_bsums[i >> 10];
        g_offs[i] = v;
        g_cursor[i] = v;
    }
    if (i == NN) g_offs[NN] = EE;
}

__global__ void scatter_k(const int* __restrict__ src, const int* __restrict__ dst) {
    int i = blockIdx.x * blockDim.x + threadIdx.x;
    if (i < EE) {
        int d = dst[i];
        int pos = atomicAdd(&g_cursor[d], 1);
        g_csr[pos] = src[i];
    }
}

// ---------------- dense: H = X@W, a_s = H.att_s, a_d = H.att_d -------------
__global__ void __launch_bounds__(64) gemm_att_k(
    const float* __restrict__ X, const float* __restrict__ W,
    const float* __restrict__ attS, const float* __restrict__ attD,
    float* __restrict__ H, float* __restrict__ AS, float* __restrict__ AD)
{
    __shared__ float sW[64 * 64];
    __shared__ float sX[64 * 65];
    __shared__ float sAtt[128];
    int tid = threadIdx.x;
    int rowBase = blockIdx.x * 64;
    int rowsValid = NN - rowBase; if (rowsValid > 64) rowsValid = 64;

    for (int i = tid; i < 1024; i += 64)
        ((float4*)sW)[i] = ((const float4*)W)[i];
    sAtt[tid] = attS[tid & 63 ? tid : 0] , sAtt[tid] = attS[tid]; // (overwritten below properly)
    sAtt[tid] = attS[tid];
    sAtt[64 + tid] = attD[tid];
    for (int i = tid; i < rowsValid * 64; i += 64) {
        int rr = i >> 6, kk = i & 63;
        sX[rr * 65 + kk] = X[(size_t)rowBase * 64 + i];
    }
    __syncthreads();

    if (tid < rowsValid) {
        float acc[64];
        #pragma unroll
        for (int c = 0; c < 64; c++) acc[c] = 0.f;
        #pragma unroll 8
        for (int k = 0; k < 64; k++) {
            float xk = sX[tid * 65 + k];
            const float4* wrow = (const float4*)(sW + k * 64);
            #pragma unroll
            for (int c4 = 0; c4 < 16; c4++) {
                float4 w = wrow[c4];
                acc[c4 * 4 + 0] = fmaf(xk, w.x, acc[c4 * 4 + 0]);
                acc[c4 * 4 + 1] = fmaf(xk, w.y, acc[c4 * 4 + 1]);
                acc[c4 * 4 + 2] = fmaf(xk, w.z, acc[c4 * 4 + 2]);
                acc[c4 * 4 + 3] = fmaf(xk, w.w, acc[c4 * 4 + 3]);
            }
        }
        float as = 0.f, ad = 0.f;
        #pragma unroll
        for (int c = 0; c < 64; c++) {
            as = fmaf(acc[c], sAtt[c], as);
            ad = fmaf(acc[c], sAtt[64 + c], ad);
        }
        int r = rowBase + tid;
        AS[r] = as;
        AD[r] = ad;
        // stage result in own sX row (read-before-write is same-thread only)
        #pragma unroll
        for (int c = 0; c < 64; c++) sX[tid * 65 + c] = acc[c];
    }
    __syncthreads();
    for (int i = tid; i < rowsValid * 64; i += 64) {
        int rr = i >> 6, cc = i & 63;
        H[(size_t)rowBase * 64 + i] = sX[rr * 65 + cc];
    }
}

// ---------------- sparse: per-dst online softmax + aggregate ---------------
__global__ void __launch_bounds__(256) aggregate_k(
    const float* __restrict__ H,
    const float* __restrict__ bias,
    float* __restrict__ OUT, int do_relu)
{
    int gw = (blockIdx.x * blockDim.x + threadIdx.x) >> 5;
    int lane = threadIdx.x & 31;
    if (gw >= NN) return;
    int dst = gw;
    int j0 = g_offs[dst], j1 = g_offs[dst + 1];
    float ad = g_ad[dst];
    float m = -INFINITY, s = 0.f, a0 = 0.f, a1 = 0.f;
    for (int j = j0; j < j1; j++) {
        int srcn = g_csr[j];
        float ev = g_as[srcn] + ad;
        ev = ev > 0.f ? ev : 0.2f * ev;
        if (ev > m) {
            float sc = __expf(m - ev);   // exp(-inf)=0 on first edge
            s *= sc; a0 *= sc; a1 *= sc;
            m = ev;
        }
        float w = __expf(ev - m);
        s += w;
        const float* hp = H + (size_t)srcn * 64;
        a0 = fmaf(w, hp[lane], a0);
        a1 = fmaf(w, hp[lane + 32], a1);
    }
    float inv = 1.f / (s + 1e-16f);
    float o0 = fmaf(a0, inv, 0.f) + bias[lane];
    float o1 = fmaf(a1, inv, 0.f) + bias[lane + 32];
    if (do_relu) { o0 = fmaxf(o0, 0.f); o1 = fmaxf(o1, 0.f); }
    OUT[(size_t)dst * 64 + lane] = o0;
    OUT[(size_t)dst * 64 + lane + 32] = o1;
}

// ---------------- launch ---------------------------------------------------
extern "C" void kernel_launch(void* const* d_in, const int* in_sizes, int n_in,
                              void* d_out, int out_size)
{
    const float* x   = (const float*)d_in[0];
    const int*   ei  = (const int*)  d_in[1];
    const float* W1  = (const float*)d_in[2];
    const float* as1 = (const float*)d_in[3];
    const float* ad1 = (const float*)d_in[4];
    const float* b1  = (const float*)d_in[5];
    const float* W2  = (const float*)d_in[6];
    const float* as2 = (const float*)d_in[7];
    const float* ad2 = (const float*)d_in[8];
    const float* b2  = (const float*)d_in[9];
    float* out = (float*)d_out;

    const int* src = ei;
    const int* dst = ei + EE;

    float *pH, *pZ, *pAS, *pAD;
    cudaGetSymbolAddress((void**)&pH,  g_h);
    cudaGetSymbolAddress((void**)&pZ,  g_z);
    cudaGetSymbolAddress((void**)&pAS, g_as);
    cudaGetSymbolAddress((void**)&pAD, g_ad);

    // CSR build (shared by both layers)
    zero_counts_k<<<(NN + 255) / 256, 256>>>();
    hist_k<<<EE / 256, 256>>>(dst);
    scanA_k<<<(NN + 1023) / 1024, 256>>>();
    scanB_k<<<1, 128>>>((NN + 1023) / 1024);
    scanC_k<<<(NN + 256) / 256, 256>>>();
    scatter_k<<<EE / 256, 256>>>(src, dst);

    // layer 1
    gemm_att_k<<<(NN + 63) / 64, 64>>>(x, W1, as1, ad1, pH, pAS, pAD);
    aggregate_k<<<(NN * 32) / 256, 256>>>(pH, b1, pZ, 1);

    // layer 2
    gemm_att_k<<<(NN + 63) / 64, 64>>>(pZ, W2, as2, ad2, pH, pAS, pAD);
    aggregate_k<<<(NN * 32) / 256, 256>>>(pH, b2, out, 0);
}

// round 2
// speedup vs baseline: 1.2647x; 1.2647x over previous
#include <cuda_runtime.h>
#include <math.h>

#define NN 100000
#define EE 1600000
#define DD 64

// ---------------- scratch (device globals; no allocation allowed) ----------
__device__ float g_h[(size_t)NN * DD];   // X@W for current layer
__device__ float g_z[(size_t)NN * DD];   // layer-1 output (relu'd)
__device__ float g_as[NN];
__device__ float g_ad[NN];
__device__ int   g_counts[NN];
__device__ int   g_offs[NN + 1];
__device__ int   g_cursor[NN];
__device__ int   g_csr[EE];              // src node ids, grouped by dst
__device__ int   g_bsums[128];

// ---------------- packed f32x2 helpers -------------------------------------
__device__ __forceinline__ unsigned long long dup2(float v) {
    unsigned long long r;
    asm("mov.b64 %0, {%1, %1};" : "=l"(r) : "f"(v));
    return r;
}
__device__ __forceinline__ unsigned long long fma2(unsigned long long a,
                                                   unsigned long long b,
                                                   unsigned long long c) {
    unsigned long long d;
    asm("fma.rn.f32x2 %0, %1, %2, %3;" : "=l"(d) : "l"(a), "l"(b), "l"(c));
    return d;
}
__device__ __forceinline__ void unpack2(unsigned long long v, float& lo, float& hi) {
    asm("mov.b64 {%0, %1}, %2;" : "=f"(lo), "=f"(hi) : "l"(v));
}

// ---------------- CSR build ------------------------------------------------
__global__ void hist_k(const int4* __restrict__ dst4) {
    int i = blockIdx.x * blockDim.x + threadIdx.x;
    if (i < EE / 4) {
        int4 d = dst4[i];
        atomicAdd(&g_counts[d.x], 1);
        atomicAdd(&g_counts[d.y], 1);
        atomicAdd(&g_counts[d.z], 1);
        atomicAdd(&g_counts[d.w], 1);
    }
}

// scanA: blocks of 1024 elems (256 thr x 4)
__global__ void scanA_k() {
    __shared__ int warpSums[8];
    int b = blockIdx.x, t = threadIdx.x;
    int base = b * 1024 + t * 4;
    int c0 = (base + 0 < NN) ? g_counts[base + 0] : 0;
    int c1 = (base + 1 < NN) ? g_counts[base + 1] : 0;
    int c2 = (base + 2 < NN) ? g_counts[base + 2] : 0;
    int c3 = (base + 3 < NN) ? g_counts[base + 3] : 0;
    int tsum = c0 + c1 + c2 + c3;
    int lane = t & 31, wid = t >> 5;
    int v = tsum;
    #pragma unroll
    for (int d = 1; d < 32; d <<= 1) {
        int n = __shfl_up_sync(0xffffffffu, v, d);
        if (lane >= d) v += n;
    }
    if (lane == 31) warpSums[wid] = v;
    __syncthreads();
    if (wid == 0 && lane < 8) {
        int wv = warpSums[lane];
        #pragma unroll
        for (int d = 1; d < 8; d <<= 1) {
            int n = __shfl_up_sync(0xffu, wv, d);
            if (lane >= d) wv += n;
        }
        warpSums[lane] = wv;
    }
    __syncthreads();
    int exc = v - tsum + (wid > 0 ? warpSums[wid - 1] : 0);
    if (base + 0 < NN) g_offs[base + 0] = exc;
    if (base + 1 < NN) g_offs[base + 1] = exc + c0;
    if (base + 2 < NN) g_offs[base + 2] = exc + c0 + c1;
    if (base + 3 < NN) g_offs[base + 3] = exc + c0 + c1 + c2;
    if (t == 255) g_bsums[b] = warpSums[7];
}

__global__ void scanB_k(int nblocks) {
    __shared__ int sm[128];
    int t = threadIdx.x;
    sm[t] = (t < nblocks) ? g_bsums[t] : 0;
    __syncthreads();
    #pragma unroll
    for (int d = 1; d < 128; d <<= 1) {
        int v = (t >= d) ? sm[t - d] : 0;
        __syncthreads();
        sm[t] += v;
        __syncthreads();
    }
    if (t < nblocks) g_bsums[t] = (t == 0) ? 0 : sm[t - 1];
}

__global__ void scanC_k() {
    int i = blockIdx.x * blockDim.x + threadIdx.x;
    if (i < NN) {
        int v = g_offs[i] + g_bsums[i >> 10];
        g_offs[i] = v;
        g_cursor[i] = v;
    }
    if (i == NN) g_offs[NN] = EE;
}

__global__ void scatter_k(const int* __restrict__ src, const int* __restrict__ dst) {
    int i = blockIdx.x * blockDim.x + threadIdx.x;
    if (i < EE) {
        int d = dst[i];
        int pos = atomicAdd(&g_cursor[d], 1);
        g_csr[pos] = src[i];
    }
}

// ---------------- dense: H = X@W, a_s = H.attS, a_d = H.attD ---------------
// 256 threads, 64 rows x 64 cols per block, 4x4 tile/thread, packed f32x2.
__global__ void __launch_bounds__(256) gemm_att_k(
    const float* __restrict__ X, const float* __restrict__ W,
    const float* __restrict__ attS, const float* __restrict__ attD,
    float* __restrict__ H, float* __restrict__ AS, float* __restrict__ AD)
{
    __shared__ float sW[64 * 64];       // [k][c]
    __shared__ float sXT[64 * 66];      // [k][r], padded to 66
    __shared__ float sAtt[128];
    int tid = threadIdx.x;
    int rowBase = blockIdx.x * 64;

    // load W (4096 floats) via float4
    #pragma unroll
    for (int i = 0; i < 4; i++)
        ((float4*)sW)[tid + 256 * i] = ((const float4*)W)[tid + 256 * i];
    if (tid < 128) sAtt[tid] = (tid < 64) ? attS[tid] : attD[tid - 64];

    // load X tile, store transposed
    {
        int r = tid >> 2;             // 0..63
        int k0 = (tid & 3) * 16;      // 0,16,32,48
        int grow = rowBase + r;
        bool rv = grow < NN;
        const float4* xp = (const float4*)(X + (size_t)(rv ? grow : 0) * 64);
        #pragma unroll
        for (int i = 0; i < 4; i++) {
            float4 v = rv ? xp[(k0 >> 2) + i] : make_float4(0.f, 0.f, 0.f, 0.f);
            int kb = k0 + 4 * i;
            sXT[(kb + 0) * 66 + r] = v.x;
            sXT[(kb + 1) * 66 + r] = v.y;
            sXT[(kb + 2) * 66 + r] = v.z;
            sXT[(kb + 3) * 66 + r] = v.w;
        }
    }
    __syncthreads();

    int cg = (tid & 15) * 4;      // col group
    int rg = (tid >> 4) * 4;      // row group

    unsigned long long acc[2][4];
    #pragma unroll
    for (int a = 0; a < 2; a++)
        #pragma unroll
        for (int b = 0; b < 4; b++) acc[a][b] = 0ull;

    #pragma unroll 4
    for (int k = 0; k < 64; k++) {
        const float* xb = &sXT[k * 66 + rg];
        unsigned long long x01 = *(const unsigned long long*)(xb);
        unsigned long long x23 = *(const unsigned long long*)(xb + 2);
        float4 wv = *(const float4*)(&sW[(k << 6) + cg]);
        unsigned long long w0 = dup2(wv.x), w1 = dup2(wv.y);
        unsigned long long w2 = dup2(wv.z), w3 = dup2(wv.w);
        acc[0][0] = fma2(x01, w0, acc[0][0]);
        acc[0][1] = fma2(x01, w1, acc[0][1]);
        acc[0][2] = fma2(x01, w2, acc[0][2]);
        acc[0][3] = fma2(x01, w3, acc[0][3]);
        acc[1][0] = fma2(x23, w0, acc[1][0]);
        acc[1][1] = fma2(x23, w1, acc[1][1]);
        acc[1][2] = fma2(x23, w2, acc[1][2]);
        acc[1][3] = fma2(x23, w3, acc[1][3]);
    }

    // unpack 4x4 tile
    float hv[4][4];
    #pragma unroll
    for (int rp = 0; rp < 2; rp++)
        #pragma unroll
        for (int c = 0; c < 4; c++)
            unpack2(acc[rp][c], hv[2 * rp][c], hv[2 * rp + 1][c]);

    // per-row attention partials over our 4 cols
    float pas[4], pad_[4];
    #pragma unroll
    for (int r = 0; r < 4; r++) {
        float s = 0.f, d = 0.f;
        #pragma unroll
        for (int c = 0; c < 4; c++) {
            s = fmaf(hv[r][c], sAtt[cg + c], s);
            d = fmaf(hv[r][c], sAtt[64 + cg + c], d);
        }
        pas[r] = s; pad_[r] = d;
    }
    // reduce across the 16 col-groups (16-lane shfl groups)
    #pragma unroll
    for (int off = 8; off >= 1; off >>= 1) {
        #pragma unroll
        for (int r = 0; r < 4; r++) {
            pas[r]  += __shfl_xor_sync(0xffffffffu, pas[r],  off, 16);
            pad_[r] += __shfl_xor_sync(0xffffffffu, pad_[r], off, 16);
        }
    }
    if ((tid & 15) == 0) {
        #pragma unroll
        for (int r = 0; r < 4; r++) {
            int grow = rowBase + rg + r;
            if (grow < NN) { AS[grow] = pas[r]; AD[grow] = pad_[r]; }
        }
    }
    // store H tile
    #pragma unroll
    for (int r = 0; r < 4; r++) {
        int grow = rowBase + rg + r;
        if (grow < NN) {
            *(float4*)(&H[(size_t)grow * 64 + cg]) =
                make_float4(hv[r][0], hv[r][1], hv[r][2], hv[r][3]);
        }
    }
}

// ---------------- sparse: per-dst softmax + aggregate (one pass) -----------
__global__ void __launch_bounds__(256) aggregate_k(
    const float* __restrict__ H,
    const float* __restrict__ bias,
    float* __restrict__ OUT, int do_relu)
{
    int gw = (blockIdx.x * blockDim.x + threadIdx.x) >> 5;
    int lane = threadIdx.x & 31;
    if (gw >= NN) return;
    int dst = gw;
    int j0 = g_offs[dst], j1 = g_offs[dst + 1];
    float ad = g_ad[dst];
    float s = 0.f, a0 = 0.f, a1 = 0.f;

    int j = j0;
    int srcn = (j < j1) ? __ldg(&g_csr[j]) : 0;
    while (j < j1) {
        int nj = j + 1;
        int nsrc = (nj < j1) ? __ldg(&g_csr[nj]) : 0;
        float e = __ldg(&g_as[srcn]) + ad;
        e = e > 0.f ? e : 0.2f * e;                 // leaky_relu
        float w = __expf(fminf(e, 70.f));           // unshifted softmax weight
        const float* hp = H + (size_t)srcn * 64;
        float h0 = __ldg(hp + lane);
        float h1 = __ldg(hp + lane + 32);
        s += w;
        a0 = fmaf(w, h0, a0);
        a1 = fmaf(w, h1, a1);
        srcn = nsrc; j = nj;
    }
    float inv = 1.f / (s + 1e-16f);
    float o0 = a0 * inv + bias[lane];
    float o1 = a1 * inv + bias[lane + 32];
    if (do_relu) { o0 = fmaxf(o0, 0.f); o1 = fmaxf(o1, 0.f); }
    OUT[(size_t)dst * 64 + lane] = o0;
    OUT[(size_t)dst * 64 + lane + 32] = o1;
}

// ---------------- launch ---------------------------------------------------
extern "C" void kernel_launch(void* const* d_in, const int* in_sizes, int n_in,
                              void* d_out, int out_size)
{
    const float* x   = (const float*)d_in[0];
    const int*   ei  = (const int*)  d_in[1];
    const float* W1  = (const float*)d_in[2];
    const float* as1 = (const float*)d_in[3];
    const float* ad1 = (const float*)d_in[4];
    const float* b1  = (const float*)d_in[5];
    const float* W2  = (const float*)d_in[6];
    const float* as2 = (const float*)d_in[7];
    const float* ad2 = (const float*)d_in[8];
    const float* b2  = (const float*)d_in[9];
    float* out = (float*)d_out;

    const int* src = ei;
    const int* dst = ei + EE;

    float *pH, *pZ, *pAS, *pAD; int* pCounts;
    cudaGetSymbolAddress((void**)&pH,  g_h);
    cudaGetSymbolAddress((void**)&pZ,  g_z);
    cudaGetSymbolAddress((void**)&pAS, g_as);
    cudaGetSymbolAddress((void**)&pAD, g_ad);
    cudaGetSymbolAddress((void**)&pCounts, g_counts);

    // CSR build (shared by both layers)
    cudaMemsetAsync(pCounts, 0, NN * sizeof(int));
    hist_k<<<(EE / 4 + 255) / 256, 256>>>((const int4*)dst);
    scanA_k<<<(NN + 1023) / 1024, 256>>>();
    scanB_k<<<1, 128>>>((NN + 1023) / 1024);
    scanC_k<<<(NN + 256) / 256, 256>>>();
    scatter_k<<<EE / 256, 256>>>(src, dst);

    // layer 1
    gemm_att_k<<<(NN + 63) / 64, 256>>>(x, W1, as1, ad1, pH, pAS, pAD);
    aggregate_k<<<(NN * 32) / 256, 256>>>(pH, b1, pZ, 1);

    // layer 2
    gemm_att_k<<<(NN + 63) / 64, 256>>>(pZ, W2, as2, ad2, pH, pAS, pAD);
    aggregate_k<<<(NN * 32) / 256, 256>>>(pH, b2, out, 0);
}

// round 3
// speedup vs baseline: 1.3541x; 1.0707x over previous
#include <cuda_runtime.h>
#include <cuda_fp16.h>
#include <math.h>

#define NN 100000
#define EE 1600000
#define DD 64

// ---------------- scratch (device globals; no allocation allowed) ----------
__device__ __half2 g_h16[(size_t)NN * 32];  // X@W for current layer (fp16 mirror)
__device__ float   g_z[(size_t)NN * DD];    // layer-1 output (relu'd, fp32)
__device__ float   g_as[NN];
__device__ float   g_ad[NN];
__device__ int     g_counts[NN];
__device__ int     g_offs[NN + 1];
__device__ int     g_cursor[NN];
__device__ int     g_csr[EE];               // src node ids, grouped by dst
__device__ int     g_bsums[128];

// ---------------- packed f32x2 helpers -------------------------------------
__device__ __forceinline__ unsigned long long dup2(float v) {
    unsigned long long r;
    asm("mov.b64 %0, {%1, %1};" : "=l"(r) : "f"(v));
    return r;
}
__device__ __forceinline__ unsigned long long fma2(unsigned long long a,
                                                   unsigned long long b,
                                                   unsigned long long c) {
    unsigned long long d;
    asm("fma.rn.f32x2 %0, %1, %2, %3;" : "=l"(d) : "l"(a), "l"(b), "l"(c));
    return d;
}
__device__ __forceinline__ void unpack2(unsigned long long v, float& lo, float& hi) {
    asm("mov.b64 {%0, %1}, %2;" : "=f"(lo), "=f"(hi) : "l"(v));
}

// ---------------- CSR build ------------------------------------------------
__global__ void hist_k(const int4* __restrict__ dst4) {
    int i = blockIdx.x * blockDim.x + threadIdx.x;
    if (i < EE / 4) {
        int4 d = dst4[i];
        atomicAdd(&g_counts[d.x], 1);
        atomicAdd(&g_counts[d.y], 1);
        atomicAdd(&g_counts[d.z], 1);
        atomicAdd(&g_counts[d.w], 1);
    }
}

__global__ void scanA_k() {
    __shared__ int warpSums[8];
    int b = blockIdx.x, t = threadIdx.x;
    int base = b * 1024 + t * 4;
    int c0 = (base + 0 < NN) ? g_counts[base + 0] : 0;
    int c1 = (base + 1 < NN) ? g_counts[base + 1] : 0;
    int c2 = (base + 2 < NN) ? g_counts[base + 2] : 0;
    int c3 = (base + 3 < NN) ? g_counts[base + 3] : 0;
    int tsum = c0 + c1 + c2 + c3;
    int lane = t & 31, wid = t >> 5;
    int v = tsum;
    #pragma unroll
    for (int d = 1; d < 32; d <<= 1) {
        int n = __shfl_up_sync(0xffffffffu, v, d);
        if (lane >= d) v += n;
    }
    if (lane == 31) warpSums[wid] = v;
    __syncthreads();
    if (wid == 0 && lane < 8) {
        int wv = warpSums[lane];
        #pragma unroll
        for (int d = 1; d < 8; d <<= 1) {
            int n = __shfl_up_sync(0xffu, wv, d);
            if (lane >= d) wv += n;
        }
        warpSums[lane] = wv;
    }
    __syncthreads();
    int exc = v - tsum + (wid > 0 ? warpSums[wid - 1] : 0);
    if (base + 0 < NN) g_offs[base + 0] = exc;
    if (base + 1 < NN) g_offs[base + 1] = exc + c0;
    if (base + 2 < NN) g_offs[base + 2] = exc + c0 + c1;
    if (base + 3 < NN) g_offs[base + 3] = exc + c0 + c1 + c2;
    if (t == 255) g_bsums[b] = warpSums[7];
}

__global__ void scanB_k(int nblocks) {
    __shared__ int sm[128];
    int t = threadIdx.x;
    sm[t] = (t < nblocks) ? g_bsums[t] : 0;
    __syncthreads();
    #pragma unroll
    for (int d = 1; d < 128; d <<= 1) {
        int v = (t >= d) ? sm[t - d] : 0;
        __syncthreads();
        sm[t] += v;
        __syncthreads();
    }
    if (t < nblocks) g_bsums[t] = (t == 0) ? 0 : sm[t - 1];
}

__global__ void scanC_k() {
    int i = blockIdx.x * blockDim.x + threadIdx.x;
    if (i < NN) {
        int v = g_offs[i] + g_bsums[i >> 10];
        g_offs[i] = v;
        g_cursor[i] = v;
    }
    if (i == NN) g_offs[NN] = EE;
}

__global__ void scatter_k(const int4* __restrict__ src4, const int4* __restrict__ dst4) {
    int i = blockIdx.x * blockDim.x + threadIdx.x;
    if (i < EE / 4) {
        int4 s = src4[i];
        int4 d = dst4[i];
        g_csr[atomicAdd(&g_cursor[d.x], 1)] = s.x;
        g_csr[atomicAdd(&g_cursor[d.y], 1)] = s.y;
        g_csr[atomicAdd(&g_cursor[d.z], 1)] = s.z;
        g_csr[atomicAdd(&g_cursor[d.w], 1)] = s.w;
    }
}

// ---------------- dense: H16 = fp16(X@W), a_s, a_d -------------------------
// 256 threads, 64 rows x 64 cols per block, 4x4 tile/thread, packed f32x2.
__global__ void __launch_bounds__(256) gemm_att_k(
    const float* __restrict__ X, const float* __restrict__ W,
    const float* __restrict__ attS, const float* __restrict__ attD,
    __half2* __restrict__ H16, float* __restrict__ AS, float* __restrict__ AD)
{
    __shared__ float sW[64 * 64];       // [k][c]
    __shared__ float sXT[64 * 66];      // [k][r], padded
    __shared__ float sAtt[128];
    int tid = threadIdx.x;
    int rowBase = blockIdx.x * 64;

    #pragma unroll
    for (int i = 0; i < 4; i++)
        ((float4*)sW)[tid + 256 * i] = ((const float4*)W)[tid + 256 * i];
    if (tid < 128) sAtt[tid] = (tid < 64) ? attS[tid] : attD[tid - 64];

    {
        int r = tid >> 2;
        int k0 = (tid & 3) * 16;
        int grow = rowBase + r;
        bool rv = grow < NN;
        const float4* xp = (const float4*)(X + (size_t)(rv ? grow : 0) * 64);
        #pragma unroll
        for (int i = 0; i < 4; i++) {
            float4 v = rv ? xp[(k0 >> 2) + i] : make_float4(0.f, 0.f, 0.f, 0.f);
            int kb = k0 + 4 * i;
            sXT[(kb + 0) * 66 + r] = v.x;
            sXT[(kb + 1) * 66 + r] = v.y;
            sXT[(kb + 2) * 66 + r] = v.z;
            sXT[(kb + 3) * 66 + r] = v.w;
        }
    }
    __syncthreads();

    int cg = (tid & 15) * 4;
    int rg = (tid >> 4) * 4;

    unsigned long long acc[2][4];
    #pragma unroll
    for (int a = 0; a < 2; a++)
        #pragma unroll
        for (int b = 0; b < 4; b++) acc[a][b] = 0ull;

    #pragma unroll 4
    for (int k = 0; k < 64; k++) {
        const float* xb = &sXT[k * 66 + rg];
        unsigned long long x01 = *(const unsigned long long*)(xb);
        unsigned long long x23 = *(const unsigned long long*)(xb + 2);
        float4 wv = *(const float4*)(&sW[(k << 6) + cg]);
        unsigned long long w0 = dup2(wv.x), w1 = dup2(wv.y);
        unsigned long long w2 = dup2(wv.z), w3 = dup2(wv.w);
        acc[0][0] = fma2(x01, w0, acc[0][0]);
        acc[0][1] = fma2(x01, w1, acc[0][1]);
        acc[0][2] = fma2(x01, w2, acc[0][2]);
        acc[0][3] = fma2(x01, w3, acc[0][3]);
        acc[1][0] = fma2(x23, w0, acc[1][0]);
        acc[1][1] = fma2(x23, w1, acc[1][1]);
        acc[1][2] = fma2(x23, w2, acc[1][2]);
        acc[1][3] = fma2(x23, w3, acc[1][3]);
    }

    float hv[4][4];
    #pragma unroll
    for (int rp = 0; rp < 2; rp++)
        #pragma unroll
        for (int c = 0; c < 4; c++)
            unpack2(acc[rp][c], hv[2 * rp][c], hv[2 * rp + 1][c]);

    // attention partials (fp32, before fp16 rounding)
    float pas[4], pad_[4];
    #pragma unroll
    for (int r = 0; r < 4; r++) {
        float s = 0.f, d = 0.f;
        #pragma unroll
        for (int c = 0; c < 4; c++) {
            s = fmaf(hv[r][c], sAtt[cg + c], s);
            d = fmaf(hv[r][c], sAtt[64 + cg + c], d);
        }
        pas[r] = s; pad_[r] = d;
    }
    #pragma unroll
    for (int off = 8; off >= 1; off >>= 1) {
        #pragma unroll
        for (int r = 0; r < 4; r++) {
            pas[r]  += __shfl_xor_sync(0xffffffffu, pas[r],  off, 16);
            pad_[r] += __shfl_xor_sync(0xffffffffu, pad_[r], off, 16);
        }
    }
    if ((tid & 15) == 0) {
        #pragma unroll
        for (int r = 0; r < 4; r++) {
            int grow = rowBase + rg + r;
            if (grow < NN) { AS[grow] = pas[r]; AD[grow] = pad_[r]; }
        }
    }
    // store H tile as half2 (4 halves = one 8B store per row)
    #pragma unroll
    for (int r = 0; r < 4; r++) {
        int grow = rowBase + rg + r;
        if (grow < NN) {
            union { __half2 h[2]; uint2 u; } cv;
            cv.h[0] = __floats2half2_rn(hv[r][0], hv[r][1]);
            cv.h[1] = __floats2half2_rn(hv[r][2], hv[r][3]);
            *(uint2*)(H16 + (size_t)grow * 32 + (cg >> 1)) = cv.u;
        }
    }
}

// ---------------- sparse: per-dst softmax + aggregate (one pass) -----------
// one warp per dst; lane covers output cols {2*lane, 2*lane+1}
__global__ void __launch_bounds__(256) aggregate_k(
    const __half2* __restrict__ H16,
    const float* __restrict__ bias,
    float* __restrict__ OUT, int do_relu)
{
    int dst = (blockIdx.x * blockDim.x + threadIdx.x) >> 5;
    int lane = threadIdx.x & 31;
    if (dst >= NN) return;
    int j0 = g_offs[dst], j1 = g_offs[dst + 1];
    float ad = g_ad[dst];
    float s = 0.f, a0 = 0.f, a1 = 0.f;

    int j = j0;
    for (; j + 4 <= j1; j += 4) {
        int i0 = __ldg(&g_csr[j + 0]);
        int i1 = __ldg(&g_csr[j + 1]);
        int i2 = __ldg(&g_csr[j + 2]);
        int i3 = __ldg(&g_csr[j + 3]);
        float e0 = __ldg(&g_as[i0]) + ad;
        float e1 = __ldg(&g_as[i1]) + ad;
        float e2 = __ldg(&g_as[i2]) + ad;
        float e3 = __ldg(&g_as[i3]) + ad;
        __half2 v0 = __ldg(H16 + (size_t)i0 * 32 + lane);
        __half2 v1 = __ldg(H16 + (size_t)i1 * 32 + lane);
        __half2 v2 = __ldg(H16 + (size_t)i2 * 32 + lane);
        __half2 v3 = __ldg(H16 + (size_t)i3 * 32 + lane);
        e0 = e0 > 0.f ? e0 : 0.2f * e0;
        e1 = e1 > 0.f ? e1 : 0.2f * e1;
        e2 = e2 > 0.f ? e2 : 0.2f * e2;
        e3 = e3 > 0.f ? e3 : 0.2f * e3;
        float w0 = __expf(fminf(e0, 70.f));
        float w1 = __expf(fminf(e1, 70.f));
        float w2 = __expf(fminf(e2, 70.f));
        float w3 = __expf(fminf(e3, 70.f));
        s += (w0 + w1) + (w2 + w3);
        float2 f0 = __half22float2(v0);
        float2 f1 = __half22float2(v1);
        float2 f2 = __half22float2(v2);
        float2 f3 = __half22float2(v3);
        a0 = fmaf(w0, f0.x, a0); a1 = fmaf(w0, f0.y, a1);
        a0 = fmaf(w1, f1.x, a0); a1 = fmaf(w1, f1.y, a1);
        a0 = fmaf(w2, f2.x, a0); a1 = fmaf(w2, f2.y, a1);
        a0 = fmaf(w3, f3.x, a0); a1 = fmaf(w3, f3.y, a1);
    }
    for (; j < j1; j++) {
        int i0 = __ldg(&g_csr[j]);
        float e = __ldg(&g_as[i0]) + ad;
        e = e > 0.f ? e : 0.2f * e;
        float w = __expf(fminf(e, 70.f));
        float2 f = __half22float2(__ldg(H16 + (size_t)i0 * 32 + lane));
        s += w;
        a0 = fmaf(w, f.x, a0);
        a1 = fmaf(w, f.y, a1);
    }
    float inv = 1.f / (s + 1e-16f);
    float2 bv = ((const float2*)bias)[lane];
    float o0 = a0 * inv + bv.x;
    float o1 = a1 * inv + bv.y;
    if (do_relu) { o0 = fmaxf(o0, 0.f); o1 = fmaxf(o1, 0.f); }
    ((float2*)(OUT + (size_t)dst * 64))[lane] = make_float2(o0, o1);
}

// ---------------- launch ---------------------------------------------------
extern "C" void kernel_launch(void* const* d_in, const int* in_sizes, int n_in,
                              void* d_out, int out_size)
{
    const float* x   = (const float*)d_in[0];
    const int*   ei  = (const int*)  d_in[1];
    const float* W1  = (const float*)d_in[2];
    const float* as1 = (const float*)d_in[3];
    const float* ad1 = (const float*)d_in[4];
    const float* b1  = (const float*)d_in[5];
    const float* W2  = (const float*)d_in[6];
    const float* as2 = (const float*)d_in[7];
    const float* ad2 = (const float*)d_in[8];
    const float* b2  = (const float*)d_in[9];
    float* out = (float*)d_out;

    const int* src = ei;
    const int* dst = ei + EE;

    __half2* pH16; float *pZ, *pAS, *pAD; int* pCounts;
    cudaGetSymbolAddress((void**)&pH16, g_h16);
    cudaGetSymbolAddress((void**)&pZ,   g_z);
    cudaGetSymbolAddress((void**)&pAS,  g_as);
    cudaGetSymbolAddress((void**)&pAD,  g_ad);
    cudaGetSymbolAddress((void**)&pCounts, g_counts);

    // CSR build (shared by both layers)
    cudaMemsetAsync(pCounts, 0, NN * sizeof(int));
    hist_k<<<(EE / 4 + 255) / 256, 256>>>((const int4*)dst);
    scanA_k<<<(NN + 1023) / 1024, 256>>>();
    scanB_k<<<1, 128>>>((NN + 1023) / 1024);
    scanC_k<<<(NN + 256) / 256, 256>>>();
    scatter_k<<<(EE / 4 + 255) / 256, 256>>>((const int4*)src, (const int4*)dst);

    // layer 1
    gemm_att_k<<<(NN + 63) / 64, 256>>>(x, W1, as1, ad1, pH16, pAS, pAD);
    aggregate_k<<<(NN * 32 + 255) / 256, 256>>>(pH16, b1, pZ, 1);

    // layer 2
    gemm_att_k<<<(NN + 63) / 64, 256>>>(pZ, W2, as2, ad2, pH16, pAS, pAD);
    aggregate_k<<<(NN * 32 + 255) / 256, 256>>>(pH16, b2, out, 0);
}